// round 1
// baseline (speedup 1.0000x reference)
#include <cuda_runtime.h>
#include <cstdint>

#define N_NODES_MAX 100000
#define HEADS 8
#define CH 16
#define F 128            // HEADS*CH
#define NEG_SLOPE 0.2f

// ---------------- scratch (static __device__, no allocation) ----------------
__device__ __align__(16) float g_h[(size_t)N_NODES_MAX * F];      // 51.2 MB
__device__ __align__(16) float g_accum[(size_t)N_NODES_MAX * F];  // 51.2 MB
__device__ __align__(16) float g_asrc[(size_t)N_NODES_MAX * HEADS];
__device__ __align__(16) float g_adst[(size_t)N_NODES_MAX * HEADS];
__device__ __align__(16) float g_denom[(size_t)N_NODES_MAX * HEADS];
__device__ int g_idx64;

// ---------------- kernel 0: edge_index dtype sniffer ----------------
// If the buffer really holds int64 indices, every sampled value is in [0, N).
// If it holds int32, pairs reinterpreted as int64 are >= 2^32 w.p. ~1.
__global__ void detect_dtype_kernel(const long long* __restrict__ ei, long long n64_safe) {
    int ok = 1;
    long long stride = n64_safe / 64;
    if (stride < 1) stride = 1;
    for (int i = 0; i < 64; i++) {
        long long v = ei[stride * i];
        if (v < 0 || v >= N_NODES_MAX) { ok = 0; break; }
    }
    g_idx64 = ok;
}

// ---------------- kernel 1: node transform + self-loop fold ----------------
// 128 threads/block, 32 nodes/block. Thread j owns output feature j (head j/16, ch j%16).
__global__ void __launch_bounds__(128) node_kernel(
    const float* __restrict__ x, const float* __restrict__ W,
    const float* __restrict__ att_src, const float* __restrict__ att_dst,
    int nodes)
{
    __shared__ float sW[16 * F];      // 8 KB
    __shared__ float sx[32][16];      // 2 KB
    const int t = threadIdx.x;        // 0..127
    for (int i = t; i < 16 * F; i += 128) sW[i] = W[i];

    const int base = blockIdx.x * 32;
    const int nrem = min(32, nodes - base);
    // load 32 x-rows (512 floats) as 128 float4
    if (t < (nrem * 16) / 4)
        ((float4*)&sx[0][0])[t] = ((const float4*)(x + (size_t)base * 16))[t];
    __syncthreads();

    const int head = t >> 4;
    const int c    = t & 15;
    const float as = att_src[t];   // att_src flattened [H*C] matches j layout
    const float ad = att_dst[t];

    for (int nn = 0; nn < nrem; nn++) {
        const int n = base + nn;
        float hj = 0.f;
        #pragma unroll
        for (int k = 0; k < 16; k++)
            hj = fmaf(sx[nn][k], sW[k * F + t], hj);

        // butterfly reduce over the 16 lanes of this head (all lanes end with full sum)
        float s1 = hj * as, s2 = hj * ad;
        #pragma unroll
        for (int off = 8; off; off >>= 1) {
            s1 += __shfl_xor_sync(0xffffffffu, s1, off, 16);
            s2 += __shfl_xor_sync(0xffffffffu, s2, off, 16);
        }
        float e = s1 + s2;
        e = fmaxf(e, NEG_SLOPE * e);        // leaky_relu
        const float w = __expf(e);          // self-loop weight (no max-shift needed)

        g_h[(size_t)n * F + t]     = hj;
        g_accum[(size_t)n * F + t] = w * hj;   // fold self-loop message
        if (c == 0) {
            g_denom[(size_t)n * HEADS + head] = w;   // fold self-loop denom
            g_asrc[(size_t)n * HEADS + head]  = s1;
            g_adst[(size_t)n * HEADS + head]  = s2;
        }
    }
}

// ---------------- kernel 2: edge scatter (1 warp / edge) ----------------
// lane = head*4 + chunk; each lane does one red.v4.f32 (16B) into accum[dst].
__global__ void __launch_bounds__(256) edge_kernel(
    const long long* __restrict__ ei64, const int* __restrict__ ei32, long long E)
{
    const long long e = (long long)blockIdx.x * 8 + (threadIdx.x >> 5);
    if (e >= E) return;
    const int lane = threadIdx.x & 31;

    int src, dst;
    if (g_idx64) { src = (int)ei64[e]; dst = (int)ei64[E + e]; }
    else         { src = ei32[e];      dst = ei32[E + e]; }

    const int h = lane >> 2;
    float a = g_asrc[(size_t)src * HEADS + h] + g_adst[(size_t)dst * HEADS + h];
    a = fmaxf(a, NEG_SLOPE * a);
    const float w = __expf(a);

    if ((lane & 3) == 0)
        atomicAdd(&g_denom[(size_t)dst * HEADS + h], w);

    const float4 hv = *(const float4*)&g_h[(size_t)src * F + lane * 4];
    float* p = &g_accum[(size_t)dst * F + lane * 4];
    asm volatile("red.global.add.v4.f32 [%0], {%1,%2,%3,%4};"
                 :: "l"(p), "f"(w * hv.x), "f"(w * hv.y), "f"(w * hv.z), "f"(w * hv.w)
                 : "memory");
}

// ---------------- kernel 3: finalize (1 warp / node) ----------------
__global__ void __launch_bounds__(256) finalize_kernel(
    const float* __restrict__ bias, const float* __restrict__ fc_w,
    const float* __restrict__ fc_b, float* __restrict__ out, int nodes)
{
    const int n = (blockIdx.x * blockDim.x + threadIdx.x) >> 5;
    const int lane = threadIdx.x & 31;
    if (n >= nodes) return;

    const int j0 = lane * 4;
    const float4 acc = *(const float4*)&g_accum[(size_t)n * F + j0];
    const float  d   = g_denom[(size_t)n * HEADS + (lane >> 2)];
    const float  inv = 1.f / (d + 1e-16f);
    const float4 b   = *(const float4*)&bias[j0];

    float o0 = fmaxf(fmaf(acc.x, inv, b.x), 0.f);
    float o1 = fmaxf(fmaf(acc.y, inv, b.y), 0.f);
    float o2 = fmaxf(fmaf(acc.z, inv, b.z), 0.f);
    float o3 = fmaxf(fmaf(acc.w, inv, b.w), 0.f);

    float p[5];
    #pragma unroll
    for (int k = 0; k < 5; k++) {
        p[k] = o0 * fc_w[(j0 + 0) * 5 + k]
             + o1 * fc_w[(j0 + 1) * 5 + k]
             + o2 * fc_w[(j0 + 2) * 5 + k]
             + o3 * fc_w[(j0 + 3) * 5 + k];
    }
    #pragma unroll
    for (int off = 16; off; off >>= 1) {
        #pragma unroll
        for (int k = 0; k < 5; k++)
            p[k] += __shfl_xor_sync(0xffffffffu, p[k], off);
    }
    if (lane == 0) {
        #pragma unroll
        for (int k = 0; k < 5; k++) p[k] += fc_b[k];
        float m = p[0];
        #pragma unroll
        for (int k = 1; k < 5; k++) m = fmaxf(m, p[k]);
        float s = 0.f;
        #pragma unroll
        for (int k = 0; k < 5; k++) s += __expf(p[k] - m);
        const float lse = m + logf(s);
        #pragma unroll
        for (int k = 0; k < 5; k++)
            out[(size_t)n * 5 + k] = p[k] - lse;
    }
}

// ---------------- launch ----------------
extern "C" void kernel_launch(void* const* d_in, const int* in_sizes, int n_in,
                              void* d_out, int out_size)
{
    const float* x       = (const float*)d_in[0];
    const void*  ei      = d_in[1];
    const float* W       = (const float*)d_in[2];
    const float* att_src = (const float*)d_in[3];
    const float* att_dst = (const float*)d_in[4];
    const float* bias    = (const float*)d_in[5];
    const float* fc_w    = (const float*)d_in[6];
    const float* fc_b    = (const float*)d_in[7];
    float* out = (float*)d_out;

    const int nodes = in_sizes[0] / 16;
    const long long E = (long long)in_sizes[1] / 2;

    // E int64-slots is the buffer size under the *smaller* interpretation -> safe bound
    detect_dtype_kernel<<<1, 1>>>((const long long*)ei, E);

    node_kernel<<<(nodes + 31) / 32, 128>>>(x, W, att_src, att_dst, nodes);

    const int eblocks = (int)((E + 7) / 8);
    edge_kernel<<<eblocks, 256>>>((const long long*)ei, (const int*)ei, E);

    finalize_kernel<<<(nodes * 32 + 255) / 256, 256>>>(bias, fc_w, fc_b, out, nodes);
}

// round 3
// speedup vs baseline: 2.0704x; 2.0704x over previous
#include <cuda_runtime.h>
#include <cstdint>

#define NMAX 100000
#define EMAX 1601000
#define HEADS 8
#define F 128
#define NEG_SLOPE 0.2f

// ---------------- static scratch (no allocation) ----------------
__device__ __align__(16) float g_h[(size_t)NMAX * F];        // 51.2 MB
__device__ __align__(16) float g_asrc[NMAX * HEADS];
__device__ __align__(16) float g_adst[NMAX * HEADS];
__device__ int g_cnt[NMAX];
__device__ int g_start[NMAX];
__device__ int g_cursor[NMAX];
__device__ int g_esrc[EMAX];
__device__ int g_bsum[128];
__device__ int g_boff[128];
__device__ int g_idx64;

// ---------------- kernel: edge_index dtype sniffer ----------------
__global__ void detect_dtype_kernel(const long long* __restrict__ ei, long long n64_safe) {
    int ok = 1;
    long long stride = n64_safe / 64;
    if (stride < 1) stride = 1;
    for (int i = 0; i < 64; i++) {
        long long v = ei[stride * i];
        if (v < 0 || v >= NMAX) { ok = 0; break; }
    }
    g_idx64 = ok;
}

// ---------------- node transform: h = xW, attention scalars ----------------
__global__ void __launch_bounds__(128) node_kernel(
    const float* __restrict__ x, const float* __restrict__ W,
    const float* __restrict__ att_src, const float* __restrict__ att_dst,
    int nodes)
{
    __shared__ float sW[16 * F];
    __shared__ float sx[32][16];
    const int t = threadIdx.x;
    for (int i = t; i < 16 * F; i += 128) sW[i] = W[i];

    const int base = blockIdx.x * 32;
    const int nrem = min(32, nodes - base);
    if (t < (nrem * 16) / 4)
        ((float4*)&sx[0][0])[t] = ((const float4*)(x + (size_t)base * 16))[t];
    __syncthreads();

    const int head = t >> 4;
    const int c    = t & 15;
    const float as = att_src[t];
    const float ad = att_dst[t];

    for (int nn = 0; nn < nrem; nn++) {
        const int n = base + nn;
        float hj = 0.f;
        #pragma unroll
        for (int k = 0; k < 16; k++)
            hj = fmaf(sx[nn][k], sW[k * F + t], hj);

        float s1 = hj * as, s2 = hj * ad;
        #pragma unroll
        for (int off = 8; off; off >>= 1) {
            s1 += __shfl_xor_sync(0xffffffffu, s1, off, 16);
            s2 += __shfl_xor_sync(0xffffffffu, s2, off, 16);
        }
        g_h[(size_t)n * F + t] = hj;
        if (c == 0) {
            g_asrc[n * HEADS + head] = s1;
            g_adst[n * HEADS + head] = s2;
        }
    }
}

// ---------------- CSR build ----------------
__global__ void zero_cnt_kernel(int nodes) {
    int i = blockIdx.x * blockDim.x + threadIdx.x;
    if (i < nodes) g_cnt[i] = 0;
}

__global__ void hist_kernel(const long long* __restrict__ ei64,
                            const int* __restrict__ ei32, long long E) {
    long long e = (long long)blockIdx.x * blockDim.x + threadIdx.x;
    if (e >= E) return;
    int dst = g_idx64 ? (int)ei64[E + e] : ei32[E + e];
    atomicAdd(&g_cnt[dst], 1);
}

// scan phase A: per-block sums (128 blocks x 256 threads x 4 elems = 131072 coverage)
__global__ void scanA_kernel(int nodes) {
    __shared__ int sh[256];
    int t = threadIdx.x, b = blockIdx.x;
    int base = (b * 256 + t) * 4;
    int s = 0;
    #pragma unroll
    for (int i = 0; i < 4; i++) { int j = base + i; if (j < nodes) s += g_cnt[j]; }
    sh[t] = s; __syncthreads();
    for (int off = 128; off; off >>= 1) {
        if (t < off) sh[t] += sh[t + off];
        __syncthreads();
    }
    if (t == 0) g_bsum[b] = sh[0];
}

// scan phase B: exclusive scan of 128 block sums (single block)
__global__ void scanB_kernel() {
    __shared__ int sh[128];
    int t = threadIdx.x;
    int mine = g_bsum[t];
    sh[t] = mine; __syncthreads();
    for (int off = 1; off < 128; off <<= 1) {
        int v = (t >= off) ? sh[t - off] : 0;
        __syncthreads();
        sh[t] += v;
        __syncthreads();
    }
    g_boff[t] = sh[t] - mine;
}

// scan phase C: write exclusive offsets + cursors
__global__ void scanC_kernel(int nodes) {
    __shared__ int sh[256];
    int t = threadIdx.x, b = blockIdx.x;
    int base = (b * 256 + t) * 4;
    int c[4]; int s = 0;
    #pragma unroll
    for (int i = 0; i < 4; i++) {
        c[i] = (base + i < nodes) ? g_cnt[base + i] : 0;
        s += c[i];
    }
    sh[t] = s; __syncthreads();
    for (int off = 1; off < 256; off <<= 1) {
        int v = (t >= off) ? sh[t - off] : 0;
        __syncthreads();
        sh[t] += v;
        __syncthreads();
    }
    int run = g_boff[b] + sh[t] - s;
    #pragma unroll
    for (int i = 0; i < 4; i++) {
        if (base + i < nodes) {
            g_start[base + i]  = run;
            g_cursor[base + i] = run;
            run += c[i];
        }
    }
}

__global__ void scatter_kernel(const long long* __restrict__ ei64,
                               const int* __restrict__ ei32, long long E) {
    long long e = (long long)blockIdx.x * blockDim.x + threadIdx.x;
    if (e >= E) return;
    int src, dst;
    if (g_idx64) { src = (int)ei64[e]; dst = (int)ei64[E + e]; }
    else         { src = ei32[e];      dst = ei32[E + e]; }
    int pos = atomicAdd(&g_cursor[dst], 1);
    g_esrc[pos] = src;
}

// ---------------- gather + finalize fused (1 warp / node) ----------------
__global__ void __launch_bounds__(256) gather_kernel(
    const float* __restrict__ bias, const float* __restrict__ fc_w,
    const float* __restrict__ fc_b, float* __restrict__ out, int nodes)
{
    __shared__ float sb[F];
    __shared__ float sw[5][F];
    __shared__ float sfb[5];
    const int t = threadIdx.x;
    for (int i = t; i < F; i += 256) sb[i] = bias[i];
    for (int i = t; i < 5 * F; i += 256) { int j = i / 5, k = i % 5; sw[k][j] = fc_w[i]; }
    if (t < 5) sfb[t] = fc_b[t];
    __syncthreads();

    const int n = blockIdx.x * 8 + (t >> 5);
    if (n >= nodes) return;
    const int lane = t & 31;
    const int h = lane >> 2;
    const int j0 = lane * 4;

    const float adw = g_adst[n * HEADS + h];

    // self loop
    float a = g_asrc[n * HEADS + h] + adw;
    a = fmaxf(a, NEG_SLOPE * a);
    float w = __expf(a);
    float4 hv = *(const float4*)&g_h[(size_t)n * F + j0];
    float accx = w * hv.x, accy = w * hv.y, accz = w * hv.z, accw = w * hv.w;
    float dsum = w;

    const int s0 = g_start[n];
    const int end = s0 + g_cnt[n];
    int e = s0;
    for (; e + 4 <= end; e += 4) {
        int i0 = g_esrc[e], i1 = g_esrc[e + 1], i2 = g_esrc[e + 2], i3 = g_esrc[e + 3];
        float a0 = g_asrc[i0 * HEADS + h] + adw;
        float a1 = g_asrc[i1 * HEADS + h] + adw;
        float a2 = g_asrc[i2 * HEADS + h] + adw;
        float a3 = g_asrc[i3 * HEADS + h] + adw;
        float4 v0 = *(const float4*)&g_h[(size_t)i0 * F + j0];
        float4 v1 = *(const float4*)&g_h[(size_t)i1 * F + j0];
        float4 v2 = *(const float4*)&g_h[(size_t)i2 * F + j0];
        float4 v3 = *(const float4*)&g_h[(size_t)i3 * F + j0];
        a0 = fmaxf(a0, NEG_SLOPE * a0); float w0 = __expf(a0);
        a1 = fmaxf(a1, NEG_SLOPE * a1); float w1 = __expf(a1);
        a2 = fmaxf(a2, NEG_SLOPE * a2); float w2 = __expf(a2);
        a3 = fmaxf(a3, NEG_SLOPE * a3); float w3 = __expf(a3);
        dsum += (w0 + w1) + (w2 + w3);
        accx += w0 * v0.x + w1 * v1.x + w2 * v2.x + w3 * v3.x;
        accy += w0 * v0.y + w1 * v1.y + w2 * v2.y + w3 * v3.y;
        accz += w0 * v0.z + w1 * v1.z + w2 * v2.z + w3 * v3.z;
        accw += w0 * v0.w + w1 * v1.w + w2 * v2.w + w3 * v3.w;
    }
    for (; e < end; e++) {
        int i0 = g_esrc[e];
        float a0 = g_asrc[i0 * HEADS + h] + adw;
        a0 = fmaxf(a0, NEG_SLOPE * a0);
        float w0 = __expf(a0);
        float4 v0 = *(const float4*)&g_h[(size_t)i0 * F + j0];
        dsum += w0;
        accx += w0 * v0.x; accy += w0 * v0.y; accz += w0 * v0.z; accw += w0 * v0.w;
    }

    const float inv = 1.f / (dsum + 1e-16f);
    float o0 = fmaxf(fmaf(accx, inv, sb[j0 + 0]), 0.f);
    float o1 = fmaxf(fmaf(accy, inv, sb[j0 + 1]), 0.f);
    float o2 = fmaxf(fmaf(accz, inv, sb[j0 + 2]), 0.f);
    float o3 = fmaxf(fmaf(accw, inv, sb[j0 + 3]), 0.f);

    float p[5];
    #pragma unroll
    for (int k = 0; k < 5; k++) {
        p[k] = o0 * sw[k][j0 + 0] + o1 * sw[k][j0 + 1]
             + o2 * sw[k][j0 + 2] + o3 * sw[k][j0 + 3];
    }
    #pragma unroll
    for (int off = 16; off; off >>= 1) {
        #pragma unroll
        for (int k = 0; k < 5; k++)
            p[k] += __shfl_xor_sync(0xffffffffu, p[k], off);
    }
    if (lane == 0) {
        #pragma unroll
        for (int k = 0; k < 5; k++) p[k] += sfb[k];
        float m = p[0];
        #pragma unroll
        for (int k = 1; k < 5; k++) m = fmaxf(m, p[k]);
        float s = 0.f;
        #pragma unroll
        for (int k = 0; k < 5; k++) s += __expf(p[k] - m);
        const float lse = m + logf(s);
        #pragma unroll
        for (int k = 0; k < 5; k++)
            out[(size_t)n * 5 + k] = p[k] - lse;
    }
}

// ---------------- launch ----------------
extern "C" void kernel_launch(void* const* d_in, const int* in_sizes, int n_in,
                              void* d_out, int out_size)
{
    const float* x       = (const float*)d_in[0];
    const void*  ei      = d_in[1];
    const float* W       = (const float*)d_in[2];
    const float* att_src = (const float*)d_in[3];
    const float* att_dst = (const float*)d_in[4];
    const float* bias    = (const float*)d_in[5];
    const float* fc_w    = (const float*)d_in[6];
    const float* fc_b    = (const float*)d_in[7];
    float* out = (float*)d_out;

    const int nodes = in_sizes[0] / 16;
    const long long E = (long long)in_sizes[1] / 2;
    const int eblk = (int)((E + 255) / 256);

    detect_dtype_kernel<<<1, 1>>>((const long long*)ei, E);

    zero_cnt_kernel<<<(nodes + 255) / 256, 256>>>(nodes);
    node_kernel<<<(nodes + 31) / 32, 128>>>(x, W, att_src, att_dst, nodes);

    hist_kernel<<<eblk, 256>>>((const long long*)ei, (const int*)ei, E);
    scanA_kernel<<<128, 256>>>(nodes);
    scanB_kernel<<<1, 128>>>();
    scanC_kernel<<<128, 256>>>(nodes);
    scatter_kernel<<<eblk, 256>>>((const long long*)ei, (const int*)ei, E);

    gather_kernel<<<(nodes + 7) / 8, 256>>>(bias, fc_w, fc_b, out, nodes);
}

// round 4
// speedup vs baseline: 2.2416x; 1.0827x over previous
#include <cuda_runtime.h>
#include <cuda_fp16.h>
#include <cstdint>

#define NMAX 100000
#define EMAX 1601000
#define HEADS 8
#define F 128
#define NEG_SLOPE 0.2f

// ---------------- static scratch (no allocation) ----------------
__device__ __align__(16) __half g_h[(size_t)NMAX * F];   // 25.6 MB (fp16)
__device__ __align__(16) float g_asrc[NMAX * HEADS];
__device__ __align__(16) float g_adst[NMAX * HEADS];
__device__ int g_cnt[NMAX];
__device__ int g_start[NMAX];
__device__ int g_cursor[NMAX];
__device__ int g_esrc[EMAX];
__device__ int g_bsum[128];
__device__ int g_boff[128];
__device__ int g_idx64;

// ---------------- init: zero counts + parallel dtype sniff ----------------
__global__ void init_kernel(const long long* __restrict__ ei, long long E, int nodes) {
    int i = blockIdx.x * blockDim.x + threadIdx.x;
    if (i < nodes) g_cnt[i] = 0;
    if (blockIdx.x == 0 && threadIdx.x < 32) {
        long long stride = E / 32;
        if (stride < 1) stride = 1;
        long long v = ei[stride * threadIdx.x];
        unsigned bad = __ballot_sync(0xffffffffu, v < 0 || v >= NMAX);
        if (threadIdx.x == 0) g_idx64 = (bad == 0u);
    }
}

// ---------------- node transform: h = xW (fp16 out), attention scalars ----------------
__global__ void __launch_bounds__(128) node_kernel(
    const float* __restrict__ x, const float* __restrict__ W,
    const float* __restrict__ att_src, const float* __restrict__ att_dst,
    int nodes)
{
    __shared__ float sW[16 * F];
    __shared__ float sx[32][16];
    const int t = threadIdx.x;
    for (int i = t; i < 16 * F; i += 128) sW[i] = W[i];

    const int base = blockIdx.x * 32;
    const int nrem = min(32, nodes - base);
    if (t < (nrem * 16) / 4)
        ((float4*)&sx[0][0])[t] = ((const float4*)(x + (size_t)base * 16))[t];
    __syncthreads();

    const int head = t >> 4;
    const int c    = t & 15;
    const float as = att_src[t];
    const float ad = att_dst[t];

    for (int nn = 0; nn < nrem; nn++) {
        const int n = base + nn;
        float hj = 0.f;
        #pragma unroll
        for (int k = 0; k < 16; k++)
            hj = fmaf(sx[nn][k], sW[k * F + t], hj);

        float s1 = hj * as, s2 = hj * ad;
        #pragma unroll
        for (int off = 8; off; off >>= 1) {
            s1 += __shfl_xor_sync(0xffffffffu, s1, off, 16);
            s2 += __shfl_xor_sync(0xffffffffu, s2, off, 16);
        }
        // pack adjacent lanes' values into one half2 store (4B per even lane)
        float hn = __shfl_down_sync(0xffffffffu, hj, 1);
        if ((t & 1) == 0)
            *(__half2*)&g_h[(size_t)n * F + t] = __floats2half2_rn(hj, hn);
        if (c == 0) {
            g_asrc[n * HEADS + head] = s1;
            g_adst[n * HEADS + head] = s2;
        }
    }
}

// ---------------- CSR build ----------------
__global__ void hist_kernel(const long long* __restrict__ ei64,
                            const int* __restrict__ ei32, long long E) {
    const long long base = (long long)blockIdx.x * 1024 + threadIdx.x;
    const int use64 = g_idx64;
    #pragma unroll
    for (int i = 0; i < 4; i++) {
        long long e = base + i * 256;
        if (e < E) {
            int dst = use64 ? (int)ei64[E + e] : ei32[E + e];
            atomicAdd(&g_cnt[dst], 1);
        }
    }
}

__global__ void scanA_kernel(int nodes) {
    __shared__ int sh[256];
    int t = threadIdx.x, b = blockIdx.x;
    int base = (b * 256 + t) * 4;
    int s = 0;
    #pragma unroll
    for (int i = 0; i < 4; i++) { int j = base + i; if (j < nodes) s += g_cnt[j]; }
    sh[t] = s; __syncthreads();
    for (int off = 128; off; off >>= 1) {
        if (t < off) sh[t] += sh[t + off];
        __syncthreads();
    }
    if (t == 0) g_bsum[b] = sh[0];
}

__global__ void scanB_kernel() {
    __shared__ int sh[128];
    int t = threadIdx.x;
    int mine = g_bsum[t];
    sh[t] = mine; __syncthreads();
    for (int off = 1; off < 128; off <<= 1) {
        int v = (t >= off) ? sh[t - off] : 0;
        __syncthreads();
        sh[t] += v;
        __syncthreads();
    }
    g_boff[t] = sh[t] - mine;
}

__global__ void scanC_kernel(int nodes) {
    __shared__ int sh[256];
    int t = threadIdx.x, b = blockIdx.x;
    int base = (b * 256 + t) * 4;
    int c[4]; int s = 0;
    #pragma unroll
    for (int i = 0; i < 4; i++) {
        c[i] = (base + i < nodes) ? g_cnt[base + i] : 0;
        s += c[i];
    }
    sh[t] = s; __syncthreads();
    for (int off = 1; off < 256; off <<= 1) {
        int v = (t >= off) ? sh[t - off] : 0;
        __syncthreads();
        sh[t] += v;
        __syncthreads();
    }
    int run = g_boff[b] + sh[t] - s;
    #pragma unroll
    for (int i = 0; i < 4; i++) {
        if (base + i < nodes) {
            g_start[base + i]  = run;
            g_cursor[base + i] = run;
            run += c[i];
        }
    }
}

__global__ void scatter_kernel(const long long* __restrict__ ei64,
                               const int* __restrict__ ei32, long long E) {
    const long long base = (long long)blockIdx.x * 512 + threadIdx.x;
    const int use64 = g_idx64;
    #pragma unroll
    for (int i = 0; i < 2; i++) {
        long long e = base + i * 256;
        if (e < E) {
            int src, dst;
            if (use64) { src = (int)ei64[e]; dst = (int)ei64[E + e]; }
            else       { src = ei32[e];      dst = ei32[E + e]; }
            int pos = atomicAdd(&g_cursor[dst], 1);
            g_esrc[pos] = src;
        }
    }
}

// ---------------- gather + finalize fused (1 warp / node) ----------------
__device__ __forceinline__ void acc_edge(int idx, int h, int j0, float adw,
                                         float& dsum, float& ax, float& ay,
                                         float& az, float& aw)
{
    float a = g_asrc[idx * HEADS + h] + adw;
    a = fmaxf(a, NEG_SLOPE * a);
    const float w = __expf(a);
    uint2 r = *(const uint2*)&g_h[(size_t)idx * F + j0];
    float2 lo = __half22float2(*(__half2*)&r.x);
    float2 hi = __half22float2(*(__half2*)&r.y);
    dsum += w;
    ax = fmaf(w, lo.x, ax); ay = fmaf(w, lo.y, ay);
    az = fmaf(w, hi.x, az); aw = fmaf(w, hi.y, aw);
}

__global__ void __launch_bounds__(256) gather_kernel(
    const float* __restrict__ bias, const float* __restrict__ fc_w,
    const float* __restrict__ fc_b, float* __restrict__ out, int nodes)
{
    __shared__ float sb[F];
    __shared__ float sw[5][F];
    __shared__ float sfb[5];
    const int t = threadIdx.x;
    for (int i = t; i < F; i += 256) sb[i] = bias[i];
    for (int i = t; i < 5 * F; i += 256) { int j = i / 5, k = i % 5; sw[k][j] = fc_w[i]; }
    if (t < 5) sfb[t] = fc_b[t];
    __syncthreads();

    const int n = blockIdx.x * 8 + (t >> 5);
    if (n >= nodes) return;
    const int lane = t & 31;
    const int h = lane >> 2;
    const int j0 = lane * 4;

    const float adw = g_adst[n * HEADS + h];

    float dsum = 0.f, ax = 0.f, ay = 0.f, az = 0.f, aw = 0.f;
    acc_edge(n, h, j0, adw, dsum, ax, ay, az, aw);   // self loop

    const int s0 = g_start[n];
    const int end = s0 + g_cnt[n];
    int e = s0;
    for (; e + 4 <= end; e += 4) {
        int i0 = g_esrc[e], i1 = g_esrc[e + 1], i2 = g_esrc[e + 2], i3 = g_esrc[e + 3];
        float a0 = g_asrc[i0 * HEADS + h] + adw;
        float a1 = g_asrc[i1 * HEADS + h] + adw;
        float a2 = g_asrc[i2 * HEADS + h] + adw;
        float a3 = g_asrc[i3 * HEADS + h] + adw;
        uint2 r0 = *(const uint2*)&g_h[(size_t)i0 * F + j0];
        uint2 r1 = *(const uint2*)&g_h[(size_t)i1 * F + j0];
        uint2 r2 = *(const uint2*)&g_h[(size_t)i2 * F + j0];
        uint2 r3 = *(const uint2*)&g_h[(size_t)i3 * F + j0];
        a0 = fmaxf(a0, NEG_SLOPE * a0); float w0 = __expf(a0);
        a1 = fmaxf(a1, NEG_SLOPE * a1); float w1 = __expf(a1);
        a2 = fmaxf(a2, NEG_SLOPE * a2); float w2 = __expf(a2);
        a3 = fmaxf(a3, NEG_SLOPE * a3); float w3 = __expf(a3);
        dsum += (w0 + w1) + (w2 + w3);
        float2 l0 = __half22float2(*(__half2*)&r0.x), u0 = __half22float2(*(__half2*)&r0.y);
        float2 l1 = __half22float2(*(__half2*)&r1.x), u1 = __half22float2(*(__half2*)&r1.y);
        float2 l2 = __half22float2(*(__half2*)&r2.x), u2 = __half22float2(*(__half2*)&r2.y);
        float2 l3 = __half22float2(*(__half2*)&r3.x), u3 = __half22float2(*(__half2*)&r3.y);
        ax += w0 * l0.x + w1 * l1.x + w2 * l2.x + w3 * l3.x;
        ay += w0 * l0.y + w1 * l1.y + w2 * l2.y + w3 * l3.y;
        az += w0 * u0.x + w1 * u1.x + w2 * u2.x + w3 * u3.x;
        aw += w0 * u0.y + w1 * u1.y + w2 * u2.y + w3 * u3.y;
    }
    for (; e < end; e++)
        acc_edge(g_esrc[e], h, j0, adw, dsum, ax, ay, az, aw);

    const float inv = 1.f / (dsum + 1e-16f);
    float o0 = fmaxf(fmaf(ax, inv, sb[j0 + 0]), 0.f);
    float o1 = fmaxf(fmaf(ay, inv, sb[j0 + 1]), 0.f);
    float o2 = fmaxf(fmaf(az, inv, sb[j0 + 2]), 0.f);
    float o3 = fmaxf(fmaf(aw, inv, sb[j0 + 3]), 0.f);

    float p[5];
    #pragma unroll
    for (int k = 0; k < 5; k++) {
        p[k] = o0 * sw[k][j0 + 0] + o1 * sw[k][j0 + 1]
             + o2 * sw[k][j0 + 2] + o3 * sw[k][j0 + 3];
    }
    #pragma unroll
    for (int off = 16; off; off >>= 1) {
        #pragma unroll
        for (int k = 0; k < 5; k++)
            p[k] += __shfl_xor_sync(0xffffffffu, p[k], off);
    }
    if (lane == 0) {
        #pragma unroll
        for (int k = 0; k < 5; k++) p[k] += sfb[k];
        float m = p[0];
        #pragma unroll
        for (int k = 1; k < 5; k++) m = fmaxf(m, p[k]);
        float s = 0.f;
        #pragma unroll
        for (int k = 0; k < 5; k++) s += __expf(p[k] - m);
        const float lse = m + logf(s);
        #pragma unroll
        for (int k = 0; k < 5; k++)
            out[(size_t)n * 5 + k] = p[k] - lse;
    }
}

// ---------------- launch ----------------
extern "C" void kernel_launch(void* const* d_in, const int* in_sizes, int n_in,
                              void* d_out, int out_size)
{
    const float* x       = (const float*)d_in[0];
    const void*  ei      = d_in[1];
    const float* W       = (const float*)d_in[2];
    const float* att_src = (const float*)d_in[3];
    const float* att_dst = (const float*)d_in[4];
    const float* bias    = (const float*)d_in[5];
    const float* fc_w    = (const float*)d_in[6];
    const float* fc_b    = (const float*)d_in[7];
    float* out = (float*)d_out;

    const int nodes = in_sizes[0] / 16;
    const long long E = (long long)in_sizes[1] / 2;

    init_kernel<<<(nodes + 255) / 256, 256>>>((const long long*)ei, E, nodes);
    node_kernel<<<(nodes + 31) / 32, 128>>>(x, W, att_src, att_dst, nodes);

    hist_kernel<<<(int)((E + 1023) / 1024), 256>>>((const long long*)ei, (const int*)ei, E);
    scanA_kernel<<<128, 256>>>(nodes);
    scanB_kernel<<<1, 128>>>();
    scanC_kernel<<<128, 256>>>(nodes);
    scatter_kernel<<<(int)((E + 511) / 512), 256>>>((const long long*)ei, (const int*)ei, E);

    gather_kernel<<<(nodes + 7) / 8, 256>>>(bias, fc_w, fc_b, out, nodes);
}